// round 3
// baseline (speedup 1.0000x reference)
#include <cuda_runtime.h>
#include <math.h>
#include <stdint.h>

#define BB 16384

// ---------------- device scratch (static, no allocation) ----------------
__device__ float g_Wcat[128 * 1280];            // [128][1024 MQK | 256 Wres]
__device__ float g_PR[(size_t)BB * 1280];       // per-row: P(1024) | R(256)
__device__ float g_U[(size_t)BB * 1024];        // u per head (4 x 256)
__device__ float g_S[(size_t)BB * 256];         // pre-LN scratch
__device__ float g_Z1[(size_t)BB * 256];
__device__ float g_H1[(size_t)BB * 256];

// ---------------- helpers ----------------
__device__ __forceinline__ float wsum(float v) {
#pragma unroll
  for (int o = 16; o; o >>= 1) v += __shfl_xor_sync(0xffffffffu, v, o);
  return v;
}
__device__ __forceinline__ float wmax(float v) {
#pragma unroll
  for (int o = 16; o; o >>= 1) v = fmaxf(v, __shfl_xor_sync(0xffffffffu, v, o));
  return v;
}

__device__ __forceinline__ uint32_t f2tf32(float f) {
  uint32_t u;
  asm("cvt.rna.tf32.f32 %0, %1;" : "=r"(u) : "f"(f));
  return u;
}

__device__ __forceinline__ void mma_tf32(float* d, const uint32_t* a, const uint32_t* b) {
  asm volatile(
      "mma.sync.aligned.m16n8k8.row.col.f32.tf32.tf32.f32 "
      "{%0,%1,%2,%3}, {%4,%5,%6,%7}, {%8,%9}, {%0,%1,%2,%3};"
      : "+f"(d[0]), "+f"(d[1]), "+f"(d[2]), "+f"(d[3])
      : "r"(a[0]), "r"(a[1]), "r"(a[2]), "r"(a[3]), "r"(b[0]), "r"(b[1]));
}

// FMA-pipe sincos (avoid MUFU.SIN throughput wall). Valid for |z| <~ 1e4.
__device__ __forceinline__ void fast_sincos(float z, float& s, float& c) {
  float t = rintf(z * 0.63661977236758134f);  // 2/pi
  int qi = (int)t;
  float r = fmaf(t, -1.5703125f, z);
  r = fmaf(t, -4.83751296997070312e-4f, r);
  r = fmaf(t, -7.54978995489188e-8f, r);
  float r2 = r * r;
  float sp = fmaf(r2, -1.9515296e-4f, 8.3321608e-3f);
  sp = fmaf(r2, sp, -1.6666654611e-1f);
  float sinr = fmaf(r * r2, sp, r);
  float cp = fmaf(r2, -1.388731625493765e-3f, 4.166664568298827e-2f);
  cp = fmaf(r2, cp, -0.5f);
  float cosr = fmaf(r2, cp, 1.0f);
  int qq = qi & 3;
  float ss = (qq & 1) ? cosr : sinr;
  float cc = (qq & 1) ? sinr : cosr;
  s = (qq & 2) ? -ss : ss;
  c = ((qq + 1) & 2) ? -cc : cc;
}

// ---------------- K0: MQK_h[i][j] = sum_d Wq[i,64h+d]*Wk[j,64h+d] ----------------
__global__ void __launch_bounds__(256) mqk_kernel(const float* __restrict__ Wq,
                                                  const float* __restrict__ Wk) {
  __shared__ float sWq[16 * 68];
  __shared__ float sWk[128 * 68];
  int h = blockIdx.x, is = blockIdx.y;
  int tid = threadIdx.x;
  {
    int il = tid >> 4, d4 = tid & 15;
    *(float4*)&sWq[il * 68 + d4 * 4] =
        *(const float4*)&Wq[(size_t)(is * 16 + il) * 256 + h * 64 + d4 * 4];
  }
  for (int jc = 0; jc < 2; jc++) {
    __syncthreads();
#pragma unroll
    for (int it = 0; it < 8; it++) {
      int f = tid + it * 256;
      int j = f >> 4, d4 = f & 15;
      *(float4*)&sWk[j * 68 + d4 * 4] =
          *(const float4*)&Wk[(size_t)(jc * 128 + j) * 256 + h * 64 + d4 * 4];
    }
    __syncthreads();
    int j = tid & 127, ih = tid >> 7;
#pragma unroll 1
    for (int il = ih * 8; il < ih * 8 + 8; il++) {
      float acc = 0.f;
#pragma unroll
      for (int d = 0; d < 64; d++) acc = fmaf(sWq[il * 68 + d], sWk[j * 68 + d], acc);
      g_Wcat[(size_t)(is * 16 + il) * 1280 + h * 256 + jc * 128 + j] = acc;
    }
  }
}

__global__ void copy_wres_kernel(const float* __restrict__ Wres) {
  int i = blockIdx.x, tid = threadIdx.x;
  g_Wcat[(size_t)i * 1280 + 1024 + tid] = Wres[(size_t)i * 256 + tid];
}

// ---------------- tf32 3-pass MMA GEMM ----------------
// C[M,N] = A[M,K] @ B[K,N], A row-major, B row-major.
// Fragment-permuted smem: A [kb][mb][lane][slot(4)], B [kb][nb][lane][slot(2)].
template <int BM, int BN, int NT, int WARPS_M, int WARPS_N, bool RELU>
__global__ void __launch_bounds__(NT, 2) gemm_tf32(
    const float* __restrict__ A, const float* __restrict__ B, float* __restrict__ C,
    int K, int lda, int ldb, int ldc,
    long long zA, long long zB, long long zC, const float* __restrict__ bias) {
  constexpr int MB = BM / 16;        // m16 blocks
  constexpr int NB = BN / 8;         // n8 blocks
  constexpr int WM = BM / WARPS_M;   // 64
  constexpr int WN = BN / WARPS_N;   // 32
  constexpr int MF = WM / 16;        // 4
  constexpr int NF = WN / 8;         // 4
  constexpr int ASEG = BM * 32 / (4 * NT);
  constexpr int BSEG = BN * 32 / (4 * NT);
  constexpr int BN4 = BN / 4;

  extern __shared__ uint32_t smem_u[];
  uint32_t* sAh = smem_u;                 // BM*32
  uint32_t* sAl = sAh + BM * 32;
  uint32_t* sBh = sAl + BM * 32;          // BN*32
  uint32_t* sBl = sBh + BN * 32;

  A += (size_t)blockIdx.z * zA;
  B += (size_t)blockIdx.z * zB;
  C += (size_t)blockIdx.z * zC;

  int tid = threadIdx.x;
  int wid = tid >> 5, lane = tid & 31;
  int wm = wid / WARPS_N, wn = wid % WARPS_N;
  int m0 = blockIdx.y * BM, n0 = blockIdx.x * BN;

  float acc[MF][NF][4] = {};

  int ktiles = K >> 5;
  for (int kt = 0; kt < ktiles; kt++) {
    __syncthreads();
    // ---- load A tile, convert to tf32 hi/lo, permuted STS ----
#pragma unroll
    for (int s = 0; s < ASEG; s++) {
      int seg = tid + s * NT;
      int r = seg >> 3, kq = seg & 7;
      float4 v = *(const float4*)&A[(size_t)(m0 + r) * lda + kt * 32 + kq * 4];
      float vv[4] = {v.x, v.y, v.z, v.w};
      int mb = r >> 4, rr = r & 15;
#pragma unroll
      for (int i = 0; i < 4; i++) {
        int c = kq * 4 + i;
        int kb = c >> 3, cc = c & 7;
        int ln = (rr & 7) * 4 + (cc & 3);
        int slot = (rr >> 3) | ((cc >> 2) << 1);
        int idx = ((kb * MB + mb) * 32 + ln) * 4 + slot;
        uint32_t hi = f2tf32(vv[i]);
        uint32_t lo = f2tf32(vv[i] - __uint_as_float(hi));
        sAh[idx] = hi;
        sAl[idx] = lo;
      }
    }
    // ---- load B tile ----
#pragma unroll
    for (int s = 0; s < BSEG; s++) {
      int seg = tid + s * NT;
      int kk = seg / BN4, nq = seg % BN4;
      float4 v = *(const float4*)&B[(size_t)(kt * 32 + kk) * ldb + n0 + nq * 4];
      float vv[4] = {v.x, v.y, v.z, v.w};
      int kb = kk >> 3, cc = kk & 7;
      int tig = cc & 3, slot = cc >> 2;
#pragma unroll
      for (int i = 0; i < 4; i++) {
        int n = nq * 4 + i;
        int nb = n >> 3, g = n & 7;
        int ln = g * 4 + tig;
        int idx = ((kb * NB + nb) * 32 + ln) * 2 + slot;
        uint32_t hi = f2tf32(vv[i]);
        uint32_t lo = f2tf32(vv[i] - __uint_as_float(hi));
        sBh[idx] = hi;
        sBl[idx] = lo;
      }
    }
    __syncthreads();
    // ---- compute ----
#pragma unroll
    for (int kb = 0; kb < 4; kb++) {
      uint32_t ah[MF][4], al[MF][4], bh[NF][2], bl[NF][2];
#pragma unroll
      for (int mf = 0; mf < MF; mf++) {
        int mb = wm * MF + mf;
        int base = ((kb * MB + mb) * 32 + lane) * 4;
        *(uint4*)ah[mf] = *(const uint4*)&sAh[base];
        *(uint4*)al[mf] = *(const uint4*)&sAl[base];
      }
#pragma unroll
      for (int nf = 0; nf < NF; nf++) {
        int nb = wn * NF + nf;
        int base = ((kb * NB + nb) * 32 + lane) * 2;
        *(uint2*)bh[nf] = *(const uint2*)&sBh[base];
        *(uint2*)bl[nf] = *(const uint2*)&sBl[base];
      }
#pragma unroll
      for (int mf = 0; mf < MF; mf++)
#pragma unroll
        for (int nf = 0; nf < NF; nf++) {
          mma_tf32(acc[mf][nf], ah[mf], bh[nf]);
          mma_tf32(acc[mf][nf], ah[mf], bl[nf]);
          mma_tf32(acc[mf][nf], al[mf], bh[nf]);
        }
    }
  }
  // ---- epilogue ----
  int g = lane >> 2, tg = lane & 3;
#pragma unroll
  for (int mf = 0; mf < MF; mf++) {
    int row = m0 + wm * WM + mf * 16 + g;
#pragma unroll
    for (int nf = 0; nf < NF; nf++) {
      int col = n0 + wn * WN + nf * 8 + tg * 2;
      float v0 = acc[mf][nf][0], v1 = acc[mf][nf][1];
      float v2 = acc[mf][nf][2], v3 = acc[mf][nf][3];
      if (RELU) {
        float b0 = bias[col], b1 = bias[col + 1];
        v0 = fmaxf(v0 + b0, 0.f);
        v1 = fmaxf(v1 + b1, 0.f);
        v2 = fmaxf(v2 + b0, 0.f);
        v3 = fmaxf(v3 + b1, 0.f);
      }
      float2 p0 = {v0, v1}, p1 = {v2, v3};
      *(float2*)&C[(size_t)row * ldc + col] = p0;
      *(float2*)&C[(size_t)(row + 8) * ldc + col] = p1;
    }
  }
}

// ---------------- K2: attention -> u ----------------
// one block per b, 256 threads; thread t: l = t>>3, sub = t&7 (32 kv-dims each).
__global__ void __launch_bounds__(256) attn_u_kernel(
    const float* __restrict__ x_ctx, const float* __restrict__ t_ctx,
    const float* __restrict__ freq, const float* __restrict__ phase) {
  __shared__ float kv[32 * 264];
  __shared__ float sp[1024];
  __shared__ float slog[128];
  __shared__ float sw[128];
  __shared__ float sfr[64], sph[64];
  int b = blockIdx.x, tid = threadIdx.x;
  int l = tid >> 3, sub = tid & 7;

  if (tid < 64) {
    sfr[tid] = freq[tid];
    sph[tid] = phase[tid];
  }
  *(float4*)&sp[tid * 4] = *(const float4*)&g_PR[(size_t)b * 1280 + tid * 4];
  __syncthreads();

  // x-part: 16 dims in registers + STS
  float xr[16];
  const float* xsrc = x_ctx + ((size_t)b * 32 + l) * 128 + sub * 16;
  float* kvr = &kv[l * 264];
#pragma unroll
  for (int i = 0; i < 4; i++) {
    float4 v = *(const float4*)&xsrc[i * 4];
    *(float4*)&kvr[sub * 16 + i * 4] = v;
    xr[i * 4 + 0] = v.x;
    xr[i * 4 + 1] = v.y;
    xr[i * 4 + 2] = v.z;
    xr[i * 4 + 3] = v.w;
  }
  // te-part: 8 sincos in registers + STS
  float sn[8], cs[8];
  {
    float t = t_ctx[(size_t)b * 32 + l];
    float lt = log1pf(fmaxf(t, 0.f));
#pragma unroll
    for (int i = 0; i < 8; i++) {
      int k = sub * 8 + i;
      float z = fmaf(lt, sfr[k], sph[k]);
      fast_sincos(z, sn[i], cs[i]);
    }
    float4 s0 = {sn[0], sn[1], sn[2], sn[3]}, s1 = {sn[4], sn[5], sn[6], sn[7]};
    float4 c0 = {cs[0], cs[1], cs[2], cs[3]}, c1 = {cs[4], cs[5], cs[6], cs[7]};
    *(float4*)&kvr[128 + sub * 8] = s0;
    *(float4*)&kvr[128 + sub * 8 + 4] = s1;
    *(float4*)&kvr[192 + sub * 8] = c0;
    *(float4*)&kvr[192 + sub * 8 + 4] = c1;
  }
  // logits partial: acc[h] over this thread's 32 dims
  float acc[4];
#pragma unroll
  for (int h = 0; h < 4; h++) {
    const float* ph_ = &sp[h * 256];
    float a = 0.f;
#pragma unroll
    for (int i4 = 0; i4 < 4; i4++) {
      float4 p = *(const float4*)&ph_[sub * 16 + i4 * 4];
      a = fmaf(xr[i4 * 4 + 0], p.x, a);
      a = fmaf(xr[i4 * 4 + 1], p.y, a);
      a = fmaf(xr[i4 * 4 + 2], p.z, a);
      a = fmaf(xr[i4 * 4 + 3], p.w, a);
    }
    float4 ps0 = *(const float4*)&ph_[128 + sub * 8];
    float4 ps1 = *(const float4*)&ph_[128 + sub * 8 + 4];
    float4 pc0 = *(const float4*)&ph_[192 + sub * 8];
    float4 pc1 = *(const float4*)&ph_[192 + sub * 8 + 4];
    a = fmaf(sn[0], ps0.x, a);
    a = fmaf(sn[1], ps0.y, a);
    a = fmaf(sn[2], ps0.z, a);
    a = fmaf(sn[3], ps0.w, a);
    a = fmaf(sn[4], ps1.x, a);
    a = fmaf(sn[5], ps1.y, a);
    a = fmaf(sn[6], ps1.z, a);
    a = fmaf(sn[7], ps1.w, a);
    a = fmaf(cs[0], pc0.x, a);
    a = fmaf(cs[1], pc0.y, a);
    a = fmaf(cs[2], pc0.z, a);
    a = fmaf(cs[3], pc0.w, a);
    a = fmaf(cs[4], pc1.x, a);
    a = fmaf(cs[5], pc1.y, a);
    a = fmaf(cs[6], pc1.z, a);
    a = fmaf(cs[7], pc1.w, a);
    acc[h] = a;
  }
#pragma unroll
  for (int h = 0; h < 4; h++) {
#pragma unroll
    for (int o = 4; o; o >>= 1) acc[h] += __shfl_xor_sync(0xffffffffu, acc[h], o);
  }
  if (sub < 4) slog[sub * 32 + l] = acc[sub] * 0.125f;
  __syncthreads();
  if (tid < 128) {
    int h = tid >> 5, ll = tid & 31;
    float v = slog[h * 32 + ll];
    float m = wmax(v);
    float e = __expf(v - m);
    float s = wsum(e);
    sw[h * 32 + ll] = e / s;
  }
  __syncthreads();
  // u-phase: thread owns kv-dim j = tid, all 4 heads
  {
    float a0 = 0.f, a1 = 0.f, a2 = 0.f, a3 = 0.f;
#pragma unroll
    for (int ll = 0; ll < 32; ll++) {
      float v = kv[ll * 264 + tid];
      a0 = fmaf(sw[ll], v, a0);
      a1 = fmaf(sw[32 + ll], v, a1);
      a2 = fmaf(sw[64 + ll], v, a2);
      a3 = fmaf(sw[96 + ll], v, a3);
    }
    size_t o = (size_t)b * 1024 + tid;
    g_U[o] = a0;
    g_U[o + 256] = a1;
    g_U[o + 512] = a2;
    g_U[o + 768] = a3;
  }
}

// ---------------- LN: out = LN(S + resid + bias)*gamma + beta ----------------
__global__ void __launch_bounds__(256) ln_kernel(
    const float* __restrict__ S, const float* __restrict__ resid, int ldres,
    const float* __restrict__ bias, const float* __restrict__ gamma,
    const float* __restrict__ beta, float* __restrict__ out) {
  int row = blockIdx.x * 8 + (threadIdx.x >> 5);
  int lane = threadIdx.x & 31;
  int c0 = lane * 4, c1 = 128 + lane * 4;
  float4 a0 = *(const float4*)&S[(size_t)row * 256 + c0];
  float4 a1 = *(const float4*)&S[(size_t)row * 256 + c1];
  float4 r0 = *(const float4*)&resid[(size_t)row * ldres + c0];
  float4 r1 = *(const float4*)&resid[(size_t)row * ldres + c1];
  float4 b0 = *(const float4*)&bias[c0];
  float4 b1 = *(const float4*)&bias[c1];
  float v[8];
  v[0] = a0.x + r0.x + b0.x;
  v[1] = a0.y + r0.y + b0.y;
  v[2] = a0.z + r0.z + b0.z;
  v[3] = a0.w + r0.w + b0.w;
  v[4] = a1.x + r1.x + b1.x;
  v[5] = a1.y + r1.y + b1.y;
  v[6] = a1.z + r1.z + b1.z;
  v[7] = a1.w + r1.w + b1.w;
  float s = 0.f;
#pragma unroll
  for (int j = 0; j < 8; j++) s += v[j];
  s = wsum(s);
  float mean = s * (1.f / 256.f);
  float q = 0.f;
#pragma unroll
  for (int j = 0; j < 8; j++) {
    float d = v[j] - mean;
    q += d * d;
  }
  q = wsum(q);
  float rstd = rsqrtf(q * (1.f / 256.f) + 1e-5f);
  float4 g0 = *(const float4*)&gamma[c0];
  float4 g1 = *(const float4*)&gamma[c1];
  float4 e0 = *(const float4*)&beta[c0];
  float4 e1 = *(const float4*)&beta[c1];
  float4 o0, o1;
  o0.x = (v[0] - mean) * rstd * g0.x + e0.x;
  o0.y = (v[1] - mean) * rstd * g0.y + e0.y;
  o0.z = (v[2] - mean) * rstd * g0.z + e0.z;
  o0.w = (v[3] - mean) * rstd * g0.w + e0.w;
  o1.x = (v[4] - mean) * rstd * g1.x + e1.x;
  o1.y = (v[5] - mean) * rstd * g1.y + e1.y;
  o1.z = (v[6] - mean) * rstd * g1.z + e1.z;
  o1.w = (v[7] - mean) * rstd * g1.w + e1.w;
  *(float4*)&out[(size_t)row * 256 + c0] = o0;
  *(float4*)&out[(size_t)row * 256 + c1] = o1;
}

// ---------------- launch ----------------
extern "C" void kernel_launch(void* const* d_in, const int* in_sizes, int n_in,
                              void* d_out, int out_size) {
  const float* x_u   = (const float*)d_in[0];
  const float* x_ctx = (const float*)d_in[1];
  const float* t_ctx = (const float*)d_in[2];
  const float* freq  = (const float*)d_in[3];
  const float* phase = (const float*)d_in[4];
  const float* Wq    = (const float*)d_in[5];
  const float* Wk    = (const float*)d_in[6];
  const float* Wv    = (const float*)d_in[7];
  const float* Wres  = (const float*)d_in[8];
  const float* bres  = (const float*)d_in[9];
  const float* W1    = (const float*)d_in[10];
  const float* b1    = (const float*)d_in[11];
  const float* W2    = (const float*)d_in[12];
  const float* b2    = (const float*)d_in[13];
  const float* g1    = (const float*)d_in[14];
  const float* be1   = (const float*)d_in[15];
  const float* g2    = (const float*)d_in[16];
  const float* be2   = (const float*)d_in[17];
  float* out = (float*)d_out;

  float *pWcat, *pPR, *pU, *pS, *pZ1, *pH1;
  cudaGetSymbolAddress((void**)&pWcat, g_Wcat);
  cudaGetSymbolAddress((void**)&pPR, g_PR);
  cudaGetSymbolAddress((void**)&pU, g_U);
  cudaGetSymbolAddress((void**)&pS, g_S);
  cudaGetSymbolAddress((void**)&pZ1, g_Z1);
  cudaGetSymbolAddress((void**)&pH1, g_H1);

  auto big = gemm_tf32<128, 128, 256, 2, 4, false>;
  auto bigRelu = gemm_tf32<128, 128, 256, 2, 4, true>;
  auto hs = gemm_tf32<128, 64, 128, 2, 2, false>;
  int smemBig = (128 * 32 * 2 + 128 * 32 * 2) * 4;  // 64KB
  int smemHs = (128 * 32 * 2 + 64 * 32 * 2) * 4;    // 48KB
  cudaFuncSetAttribute(big, cudaFuncAttributeMaxDynamicSharedMemorySize, smemBig);
  cudaFuncSetAttribute(bigRelu, cudaFuncAttributeMaxDynamicSharedMemorySize, smemBig);
  cudaFuncSetAttribute(hs, cudaFuncAttributeMaxDynamicSharedMemorySize, smemHs);

  // K0: build [MQK | Wres]
  mqk_kernel<<<dim3(4, 8), 256>>>(Wq, Wk);
  copy_wres_kernel<<<128, 256>>>(Wres);

  // K1: P|R = x_u @ Wcat   [16384,128] x [128,1280]
  big<<<dim3(10, 128), 256, smemBig>>>(x_u, pWcat, pPR, 128, 128, 1280, 1280,
                                       0, 0, 0, nullptr);

  // K2: attention -> u
  attn_u_kernel<<<BB, 256>>>(x_ctx, t_ctx, freq, phase);

  // K3: S = u_h @ Wv_h (per head via blockIdx.z)
  hs<<<dim3(1, 128, 4), 128, smemHs>>>(pU, Wv, pS, 256, 1024, 256, 256,
                                       256, 64, 64, nullptr);

  // K3b: z1 = LN(S + R + bres)
  ln_kernel<<<BB / 8, 256>>>(pS, pPR + 1024, 1280, bres, g1, be1, pZ1);

  // K4: h1 = relu(z1 @ W1 + b1)
  bigRelu<<<dim3(2, 128), 256, smemBig>>>(pZ1, W1, pH1, 256, 256, 256, 256,
                                          0, 0, 0, b1);

  // K5: S = h1 @ W2
  big<<<dim3(2, 128), 256, smemBig>>>(pH1, W2, pS, 256, 256, 256, 256,
                                      0, 0, 0, nullptr);

  // K5b: out = LN(S + z1 + b2)
  ln_kernel<<<BB / 8, 256>>>(pS, pZ1, 256, b2, g2, be2, out);
}

// round 4
// speedup vs baseline: 1.6994x; 1.6994x over previous
#include <cuda_runtime.h>
#include <math.h>
#include <stdint.h>

#define BB 16384

// ---------------- device scratch (static, no allocation) ----------------
__device__ float g_Wcat[128 * 1280];            // [128][1024 MQK | 256 Wres]
__device__ float g_PR[(size_t)BB * 1280];       // per-row: P(1024) | R(256)
__device__ float g_U[(size_t)BB * 1024];        // u per head (4 x 256)
__device__ float g_Z1[(size_t)BB * 256];
__device__ float g_H1[(size_t)BB * 256];

// ---------------- helpers ----------------
__device__ __forceinline__ float wsum(float v) {
#pragma unroll
  for (int o = 16; o; o >>= 1) v += __shfl_xor_sync(0xffffffffu, v, o);
  return v;
}
__device__ __forceinline__ float wmax(float v) {
#pragma unroll
  for (int o = 16; o; o >>= 1) v = fmaxf(v, __shfl_xor_sync(0xffffffffu, v, o));
  return v;
}

// packed f32x2 FMA: d = a*b + d (elementwise on 2 floats)
#define FMA2(d, a, b) \
  asm("fma.rn.f32x2 %0, %1, %2, %0;" : "+l"(d) : "l"(a), "l"(b))

__device__ __forceinline__ unsigned long long dup2(float x) {
  unsigned long long r;
  asm("mov.b64 %0, {%1, %1};" : "=l"(r) : "f"(x));
  return r;
}
__device__ __forceinline__ float2 unpk(unsigned long long p) {
  float2 r;
  asm("mov.b64 {%0, %1}, %2;" : "=f"(r.x), "=f"(r.y) : "l"(p));
  return r;
}

// FMA-pipe sincos (avoid MUFU.SIN throughput wall). Valid for |z| <~ 1e4.
__device__ __forceinline__ void fast_sincos(float z, float& s, float& c) {
  float t = rintf(z * 0.63661977236758134f);  // 2/pi
  int qi = (int)t;
  float r = fmaf(t, -1.5703125f, z);
  r = fmaf(t, -4.83751296997070312e-4f, r);
  r = fmaf(t, -7.54978995489188e-8f, r);
  float r2 = r * r;
  float sp = fmaf(r2, -1.9515296e-4f, 8.3321608e-3f);
  sp = fmaf(r2, sp, -1.6666654611e-1f);
  float sinr = fmaf(r * r2, sp, r);
  float cp = fmaf(r2, -1.388731625493765e-3f, 4.166664568298827e-2f);
  cp = fmaf(r2, cp, -0.5f);
  float cosr = fmaf(r2, cp, 1.0f);
  int qq = qi & 3;
  float ss = (qq & 1) ? cosr : sinr;
  float cc = (qq & 1) ? sinr : cosr;
  s = (qq & 2) ? -ss : ss;
  c = ((qq + 1) & 2) ? -cc : cc;
}

// ---------------- K0: MQK_h[i][j] = sum_d Wq[i,64h+d]*Wk[j,64h+d] ----------------
__global__ void __launch_bounds__(256) mqk_kernel(const float* __restrict__ Wq,
                                                  const float* __restrict__ Wk) {
  __shared__ float sWq[16 * 68];
  __shared__ float sWk[128 * 68];
  int h = blockIdx.x, is = blockIdx.y;
  int tid = threadIdx.x;
  {
    int il = tid >> 4, d4 = tid & 15;
    *(float4*)&sWq[il * 68 + d4 * 4] =
        *(const float4*)&Wq[(size_t)(is * 16 + il) * 256 + h * 64 + d4 * 4];
  }
  for (int jc = 0; jc < 2; jc++) {
    __syncthreads();
#pragma unroll
    for (int it = 0; it < 8; it++) {
      int f = tid + it * 256;
      int j = f >> 4, d4 = f & 15;
      *(float4*)&sWk[j * 68 + d4 * 4] =
          *(const float4*)&Wk[(size_t)(jc * 128 + j) * 256 + h * 64 + d4 * 4];
    }
    __syncthreads();
    int j = tid & 127, ih = tid >> 7;
#pragma unroll 1
    for (int il = ih * 8; il < ih * 8 + 8; il++) {
      float acc = 0.f;
#pragma unroll
      for (int d = 0; d < 64; d++) acc = fmaf(sWq[il * 68 + d], sWk[j * 68 + d], acc);
      g_Wcat[(size_t)(is * 16 + il) * 1280 + h * 256 + jc * 128 + j] = acc;
    }
  }
}

__global__ void copy_wres_kernel(const float* __restrict__ Wres) {
  int i = blockIdx.x, tid = threadIdx.x;
  g_Wcat[(size_t)i * 1280 + 1024 + tid] = Wres[(size_t)i * 256 + tid];
}

// ---------------- SIMT GEMM with packed f32x2 FMA, BM=64 BN=256 BK=32 ----------------
// EPI: 0 = plain store, 1 = relu(x+bias), 2 = LN(x+bias+resid)*gamma+beta (gridDim.x==1)
template <int EPI>
__global__ void __launch_bounds__(256, 2) gemm_epi(
    const float* __restrict__ A, const float* __restrict__ W, float* __restrict__ C,
    int K, int ldw, int ldc,
    const float* __restrict__ bias,
    const float* __restrict__ resid, int ldres,
    const float* __restrict__ gamma, const float* __restrict__ beta) {
  __shared__ float sA[64 * 36];
  __shared__ float sB[32 * 256];
  int tid = threadIdx.x;
  int m0 = blockIdx.y * 64, n0 = blockIdx.x * 256;
  int r0 = (tid >> 5) * 8, c0 = (tid & 31) * 8;
  unsigned long long accP[8][4];
#pragma unroll
  for (int i = 0; i < 8; i++)
#pragma unroll
    for (int j = 0; j < 4; j++) accP[i][j] = 0ull;

  int kt_n = K >> 5;
  for (int kt = 0; kt < kt_n; kt++) {
    __syncthreads();
#pragma unroll
    for (int it = 0; it < 2; it++) {
      int f = tid + it * 256, r = f >> 3, kq = f & 7;
      *(float4*)&sA[r * 36 + kq * 4] =
          *(const float4*)&A[(size_t)(m0 + r) * K + kt * 32 + kq * 4];
    }
#pragma unroll
    for (int it = 0; it < 8; it++) {
      int f = tid + it * 256, kk = f >> 6, c4 = f & 63;
      *(float4*)&sB[kk * 256 + c4 * 4] =
          *(const float4*)&W[(size_t)(kt * 32 + kk) * ldw + n0 + c4 * 4];
    }
    __syncthreads();
#pragma unroll
    for (int kk = 0; kk < 32; kk++) {
      ulonglong2 q0 = *(const ulonglong2*)&sB[kk * 256 + c0];
      ulonglong2 q1 = *(const ulonglong2*)&sB[kk * 256 + c0 + 4];
      unsigned long long bP[4] = {q0.x, q0.y, q1.x, q1.y};
#pragma unroll
      for (int i = 0; i < 8; i++) {
        unsigned long long aD = dup2(sA[(r0 + i) * 36 + kk]);
        FMA2(accP[i][0], aD, bP[0]);
        FMA2(accP[i][1], aD, bP[1]);
        FMA2(accP[i][2], aD, bP[2]);
        FMA2(accP[i][3], aD, bP[3]);
      }
    }
  }
  // ---- epilogue ----
  float bb[8], gg[8], ee[8];
  if (EPI >= 1) {
#pragma unroll
    for (int j = 0; j < 8; j++) bb[j] = bias[n0 + c0 + j];
  }
  if (EPI == 2) {
#pragma unroll
    for (int j = 0; j < 8; j++) {
      gg[j] = gamma[n0 + c0 + j];
      ee[j] = beta[n0 + c0 + j];
    }
  }
#pragma unroll
  for (int i = 0; i < 8; i++) {
    size_t row = (size_t)(m0 + r0 + i);
    float v[8];
#pragma unroll
    for (int j2 = 0; j2 < 4; j2++) {
      float2 u = unpk(accP[i][j2]);
      v[2 * j2] = u.x;
      v[2 * j2 + 1] = u.y;
    }
    if (EPI == 1) {
#pragma unroll
      for (int j = 0; j < 8; j++) v[j] = fmaxf(v[j] + bb[j], 0.f);
    } else if (EPI == 2) {
      float4 rr0 = *(const float4*)&resid[row * ldres + c0];
      float4 rr1 = *(const float4*)&resid[row * ldres + c0 + 4];
      float rj[8] = {rr0.x, rr0.y, rr0.z, rr0.w, rr1.x, rr1.y, rr1.z, rr1.w};
#pragma unroll
      for (int j = 0; j < 8; j++) v[j] = v[j] + bb[j] + rj[j];
      float s = 0.f;
#pragma unroll
      for (int j = 0; j < 8; j++) s += v[j];
      s = wsum(s);
      float mean = s * (1.f / 256.f);
      float q = 0.f;
#pragma unroll
      for (int j = 0; j < 8; j++) {
        float d = v[j] - mean;
        q += d * d;
      }
      q = wsum(q);
      float rstd = rsqrtf(q * (1.f / 256.f) + 1e-5f);
#pragma unroll
      for (int j = 0; j < 8; j++) v[j] = (v[j] - mean) * rstd * gg[j] + ee[j];
    }
    float4 o0 = {v[0], v[1], v[2], v[3]};
    float4 o1 = {v[4], v[5], v[6], v[7]};
    *(float4*)&C[row * ldc + n0 + c0] = o0;
    *(float4*)&C[row * ldc + n0 + c0 + 4] = o1;
  }
}

// ---------------- K2: attention -> u (conflict-free smem) ----------------
// one block per b, 256 threads; thread t: l = t>>3, sub = t&7 (32 kv-dims each).
// kv rows padded to 260 floats; p repacked to [h][sub] 36-float blocks.
__global__ void __launch_bounds__(256) attn_u_kernel(
    const float* __restrict__ x_ctx, const float* __restrict__ t_ctx,
    const float* __restrict__ freq, const float* __restrict__ phase) {
  __shared__ float kv[32 * 260];
  __shared__ float p2[4 * 8 * 36];
  __shared__ float slog[128];
  __shared__ float sw[128];
  __shared__ float sfr[64], sph[64];
  int b = blockIdx.x, tid = threadIdx.x;
  int l = tid >> 3, sub = tid & 7;

  if (tid < 64) {
    sfr[tid] = freq[tid];
    sph[tid] = phase[tid];
  }
  // repack p: block (h, s2) holds 8 float4 chunks: c0-3 = x dims s2*16..+15,
  // c4-5 = sin dims 128+s2*8..+7, c6-7 = cos dims 192+s2*8..+7
  {
    int h = tid >> 6, r = tid & 63, s2 = r >> 3, c = r & 7;
    int idx4;
    if (c < 4) idx4 = h * 64 + s2 * 4 + c;
    else if (c < 6) idx4 = h * 64 + 32 + s2 * 2 + (c - 4);
    else idx4 = h * 64 + 48 + s2 * 2 + (c - 6);
    float4 v = *(const float4*)&g_PR[(size_t)b * 1280 + (size_t)idx4 * 4];
    *(float4*)&p2[(h * 8 + s2) * 36 + c * 4] = v;
  }
  __syncthreads();

  float acc[4] = {0.f, 0.f, 0.f, 0.f};
  const float* xsrc = x_ctx + ((size_t)b * 32 + l) * 128 + sub * 16;
  float* kvrow = kv + l * 260;

  // x-part: stream 4 chunks: LDG -> STS -> FMA vs p2
#pragma unroll
  for (int c = 0; c < 4; c++) {
    float4 v = *(const float4*)&xsrc[c * 4];
    *(float4*)&kvrow[sub * 16 + c * 4] = v;
#pragma unroll
    for (int h = 0; h < 4; h++) {
      float4 p = *(const float4*)&p2[(h * 8 + sub) * 36 + c * 4];
      acc[h] = fmaf(v.x, p.x, acc[h]);
      acc[h] = fmaf(v.y, p.y, acc[h]);
      acc[h] = fmaf(v.z, p.z, acc[h]);
      acc[h] = fmaf(v.w, p.w, acc[h]);
    }
  }
  // te-part
  {
    float t = t_ctx[(size_t)b * 32 + l];
    float lt = log1pf(fmaxf(t, 0.f));
#pragma unroll
    for (int g = 0; g < 2; g++) {  // g=0: k=sub*8..+3 (c4,c6); g=1: +4..7 (c5,c7)
      float4 sv, cv;
      float ss, cc;
      int k0 = sub * 8 + g * 4;
      float z0 = fmaf(lt, sfr[k0 + 0], sph[k0 + 0]);
      float z1 = fmaf(lt, sfr[k0 + 1], sph[k0 + 1]);
      float z2 = fmaf(lt, sfr[k0 + 2], sph[k0 + 2]);
      float z3 = fmaf(lt, sfr[k0 + 3], sph[k0 + 3]);
      fast_sincos(z0, ss, cc); sv.x = ss; cv.x = cc;
      fast_sincos(z1, ss, cc); sv.y = ss; cv.y = cc;
      fast_sincos(z2, ss, cc); sv.z = ss; cv.z = cc;
      fast_sincos(z3, ss, cc); sv.w = ss; cv.w = cc;
      *(float4*)&kvrow[128 + sub * 8 + g * 4] = sv;
      *(float4*)&kvrow[192 + sub * 8 + g * 4] = cv;
#pragma unroll
      for (int h = 0; h < 4; h++) {
        float4 ps = *(const float4*)&p2[(h * 8 + sub) * 36 + (4 + g) * 4];
        float4 pc = *(const float4*)&p2[(h * 8 + sub) * 36 + (6 + g) * 4];
        acc[h] = fmaf(sv.x, ps.x, acc[h]);
        acc[h] = fmaf(sv.y, ps.y, acc[h]);
        acc[h] = fmaf(sv.z, ps.z, acc[h]);
        acc[h] = fmaf(sv.w, ps.w, acc[h]);
        acc[h] = fmaf(cv.x, pc.x, acc[h]);
        acc[h] = fmaf(cv.y, pc.y, acc[h]);
        acc[h] = fmaf(cv.z, pc.z, acc[h]);
        acc[h] = fmaf(cv.w, pc.w, acc[h]);
      }
    }
  }
  // reduce over sub (8 lanes)
#pragma unroll
  for (int h = 0; h < 4; h++) {
#pragma unroll
    for (int o = 4; o; o >>= 1) acc[h] += __shfl_xor_sync(0xffffffffu, acc[h], o);
  }
  if (sub < 4) slog[sub * 32 + l] = acc[sub] * 0.125f;
  __syncthreads();
  if (tid < 128) {
    float v = slog[tid];
    float m = wmax(v);
    float e = __expf(v - m);
    float s = wsum(e);
    sw[tid] = e / s;
  }
  __syncthreads();
  // u-phase: thread owns kv-dim j = tid, all 4 heads
  {
    float a0 = 0.f, a1 = 0.f, a2 = 0.f, a3 = 0.f;
#pragma unroll
    for (int ll = 0; ll < 32; ll++) {
      float v = kv[ll * 260 + tid];
      a0 = fmaf(sw[ll], v, a0);
      a1 = fmaf(sw[32 + ll], v, a1);
      a2 = fmaf(sw[64 + ll], v, a2);
      a3 = fmaf(sw[96 + ll], v, a3);
    }
    size_t o = (size_t)b * 1024 + tid;
    g_U[o] = a0;
    g_U[o + 256] = a1;
    g_U[o + 512] = a2;
    g_U[o + 768] = a3;
  }
}

// ---------------- K3: head-split GEMM agg = u_h @ Wv[:,h*64..] + LN epilogue ----------
// BM=64, BN=256 (4 heads x 64), BK=16, 256 threads, grid (1, B/64)
__global__ void __launch_bounds__(256, 2) gemm_hs_ln(
    const float* __restrict__ Wv, float* __restrict__ C,
    const float* __restrict__ bias, const float* __restrict__ resid, int ldres,
    const float* __restrict__ gamma, const float* __restrict__ beta) {
  __shared__ float sA[64 * 80];
  __shared__ float sB[16 * 256];
  int tid = threadIdx.x;
  int m0 = blockIdx.y * 64;
  int r0 = (tid >> 5) * 8, c0 = (tid & 31) * 8, hh = c0 >> 6;
  unsigned long long accP[8][4];
#pragma unroll
  for (int i = 0; i < 8; i++)
#pragma unroll
    for (int j = 0; j < 4; j++) accP[i][j] = 0ull;

  for (int kt = 0; kt < 16; kt++) {
    __syncthreads();
#pragma unroll
    for (int it = 0; it < 4; it++) {
      int f = tid + it * 256;  // 0..1023
      int r = f >> 4, q = f & 15;
      int h = q >> 2, kq = q & 3;
      *(float4*)&sA[r * 80 + h * 20 + kq * 4] =
          *(const float4*)&g_U[(size_t)(m0 + r) * 1024 + h * 256 + kt * 16 + kq * 4];
    }
#pragma unroll
    for (int it = 0; it < 4; it++) {
      int f = tid + it * 256;
      int kk = f >> 6, c4 = f & 63;
      *(float4*)&sB[kk * 256 + c4 * 4] =
          *(const float4*)&Wv[(size_t)(kt * 16 + kk) * 256 + c4 * 4];
    }
    __syncthreads();
#pragma unroll
    for (int kk = 0; kk < 16; kk++) {
      ulonglong2 q0 = *(const ulonglong2*)&sB[kk * 256 + c0];
      ulonglong2 q1 = *(const ulonglong2*)&sB[kk * 256 + c0 + 4];
      unsigned long long bP[4] = {q0.x, q0.y, q1.x, q1.y};
#pragma unroll
      for (int i = 0; i < 8; i++) {
        unsigned long long aD = dup2(sA[(r0 + i) * 80 + hh * 20 + kk]);
        FMA2(accP[i][0], aD, bP[0]);
        FMA2(accP[i][1], aD, bP[1]);
        FMA2(accP[i][2], aD, bP[2]);
        FMA2(accP[i][3], aD, bP[3]);
      }
    }
  }
  // ---- LN epilogue: LN(acc + bias + resid) * gamma + beta ----
  float bb[8], gg[8], ee[8];
#pragma unroll
  for (int j = 0; j < 8; j++) {
    bb[j] = bias[c0 + j];
    gg[j] = gamma[c0 + j];
    ee[j] = beta[c0 + j];
  }
#pragma unroll
  for (int i = 0; i < 8; i++) {
    size_t row = (size_t)(m0 + r0 + i);
    float v[8];
#pragma unroll
    for (int j2 = 0; j2 < 4; j2++) {
      float2 u = unpk(accP[i][j2]);
      v[2 * j2] = u.x;
      v[2 * j2 + 1] = u.y;
    }
    float4 rr0 = *(const float4*)&resid[row * ldres + c0];
    float4 rr1 = *(const float4*)&resid[row * ldres + c0 + 4];
    float rj[8] = {rr0.x, rr0.y, rr0.z, rr0.w, rr1.x, rr1.y, rr1.z, rr1.w};
#pragma unroll
    for (int j = 0; j < 8; j++) v[j] = v[j] + bb[j] + rj[j];
    float s = 0.f;
#pragma unroll
    for (int j = 0; j < 8; j++) s += v[j];
    s = wsum(s);
    float mean = s * (1.f / 256.f);
    float q = 0.f;
#pragma unroll
    for (int j = 0; j < 8; j++) {
      float d = v[j] - mean;
      q += d * d;
    }
    q = wsum(q);
    float rstd = rsqrtf(q * (1.f / 256.f) + 1e-5f);
#pragma unroll
    for (int j = 0; j < 8; j++) v[j] = (v[j] - mean) * rstd * gg[j] + ee[j];
    float4 o0 = {v[0], v[1], v[2], v[3]};
    float4 o1 = {v[4], v[5], v[6], v[7]};
    *(float4*)&C[row * 256 + c0] = o0;
    *(float4*)&C[row * 256 + c0 + 4] = o1;
  }
}

// ---------------- launch ----------------
extern "C" void kernel_launch(void* const* d_in, const int* in_sizes, int n_in,
                              void* d_out, int out_size) {
  const float* x_u   = (const float*)d_in[0];
  const float* x_ctx = (const float*)d_in[1];
  const float* t_ctx = (const float*)d_in[2];
  const float* freq  = (const float*)d_in[3];
  const float* phase = (const float*)d_in[4];
  const float* Wq    = (const float*)d_in[5];
  const float* Wk    = (const float*)d_in[6];
  const float* Wv    = (const float*)d_in[7];
  const float* Wres  = (const float*)d_in[8];
  const float* bres  = (const float*)d_in[9];
  const float* W1    = (const float*)d_in[10];
  const float* b1    = (const float*)d_in[11];
  const float* W2    = (const float*)d_in[12];
  const float* b2    = (const float*)d_in[13];
  const float* g1    = (const float*)d_in[14];
  const float* be1   = (const float*)d_in[15];
  const float* g2    = (const float*)d_in[16];
  const float* be2   = (const float*)d_in[17];
  float* out = (float*)d_out;

  float *pWcat, *pPR, *pU, *pZ1, *pH1;
  cudaGetSymbolAddress((void**)&pWcat, g_Wcat);
  cudaGetSymbolAddress((void**)&pPR, g_PR);
  cudaGetSymbolAddress((void**)&pU, g_U);
  cudaGetSymbolAddress((void**)&pZ1, g_Z1);
  cudaGetSymbolAddress((void**)&pH1, g_H1);

  // K0: build [MQK | Wres]
  mqk_kernel<<<dim3(4, 8), 256>>>(Wq, Wk);
  copy_wres_kernel<<<128, 256>>>(Wres);

  // K1: P|R = x_u @ Wcat   [16384,128] x [128,1280]
  gemm_epi<0><<<dim3(5, 256), 256>>>(x_u, pWcat, pPR, 128, 1280, 1280,
                                     nullptr, nullptr, 0, nullptr, nullptr);

  // K2: attention -> u
  attn_u_kernel<<<BB, 256>>>(x_ctx, t_ctx, freq, phase);

  // K3: z1 = LN(u_h @ Wv_h + R + bres)
  gemm_hs_ln<<<dim3(1, 256), 256>>>(Wv, pZ1, bres, pPR + 1024, 1280, g1, be1);

  // K4: h1 = relu(z1 @ W1 + b1)
  gemm_epi<1><<<dim3(1, 256), 256>>>(pZ1, W1, pH1, 256, 256, 256,
                                     b1, nullptr, 0, nullptr, nullptr);

  // K5: out = LN(h1 @ W2 + b2 + z1)
  gemm_epi<2><<<dim3(1, 256), 256>>>(pH1, W2, out, 256, 256, 256,
                                     b2, pZ1, 256, g2, be2);
}